// round 7
// baseline (speedup 1.0000x reference)
#include <cuda_runtime.h>
#include <math.h>

#define NN 256
#define TT 1000
#define NO_ 10
#define NS_ 10
#define DD 20      // NO_ + NS_
#define HH 64
#define GG 192     // 3*HH

typedef unsigned long long ull;

// Scratch (no allocations allowed): hidden states
__device__ float g_hs[(size_t)NN * TT * HH];   // 65.5 MB
__device__ double g_acc;
__device__ unsigned int g_done;

// ---- packed f32x2 helpers (Blackwell sm_103a) ------------------------------
__device__ __forceinline__ ull pack2(float lo, float hi) {
    ull r; asm("mov.b64 %0,{%1,%2};" : "=l"(r) : "f"(lo), "f"(hi)); return r;
}
__device__ __forceinline__ float2 unpack2(ull v) {
    float lo, hi; asm("mov.b64 {%0,%1},%2;" : "=f"(lo), "=f"(hi) : "l"(v));
    return make_float2(lo, hi);
}
__device__ __forceinline__ ull fma2(ull a, ull b, ull c) {
    ull d; asm("fma.rn.f32x2 %0,%1,%2,%3;" : "=l"(d) : "l"(a), "l"(b), "l"(c)); return d;
}
__device__ __forceinline__ ull add2(ull a, ull b) {
    ull d; asm("add.rn.f32x2 %0,%1,%2;" : "=l"(d) : "l"(a), "l"(b)); return d;
}
__device__ __forceinline__ float tanh_fast(float x) {
    float y; asm("tanh.approx.f32 %0,%1;" : "=f"(y) : "f"(x)); return y;
}
__device__ __forceinline__ float sigmoid_fast(float x) {
    return fmaf(0.5f, tanh_fast(0.5f * x), 0.5f);
}

#define BAR_SYNC_1()   asm volatile("bar.sync 1, 192;" ::: "memory")
#define BAR_ARRIVE_1() asm volatile("bar.arrive 1, 192;" ::: "memory")

// ---------------------------------------------------------------------------
// Fused GRU scan: 256 blocks x 192 threads (1 sample/block, 2 blocks/SM).
// Thread k holds Wh column k (32 f32x2 pairs) and Wi column k (10 pairs) in
// registers; x is streamed into a double-buffered shared tile with a 2-step
// prefetch; the input projection is computed inline (no g_xp scratch at all).
// Named split barrier: only gate warps (k<64) wait at phase-1.
// ---------------------------------------------------------------------------
__global__ void __launch_bounds__(GG, 2) gru_scan_kernel(
    const float* __restrict__ Yi, const float* __restrict__ Xh,
    const float* __restrict__ Wi, const float* __restrict__ Wh,
    const float* __restrict__ bi, const float* __restrict__ bh)
{
    __shared__ __align__(16) float sh_h[HH];
    __shared__ __align__(16) float sh_x[2][DD];
    __shared__ float sh_g[GG];     // xproj + hproj (+ both biases), all 192
    __shared__ float sh_hn[HH];    // hproj + bh only, n-gate columns

    const int k = threadIdx.x;
    const int n = blockIdx.x;
    if (n == 0 && k == 0) { g_acc = 0.0; g_done = 0u; }

    // weights for this output column (coalesced across threads)
    ull wh2[HH / 2];
#pragma unroll
    for (int p = 0; p < HH / 2; p++)
        wh2[p] = pack2(Wh[(2 * p) * GG + k], Wh[(2 * p + 1) * GG + k]);
    ull wi2[DD / 2];
#pragma unroll
    for (int p = 0; p < DD / 2; p++)
        wi2[p] = pack2(Wi[(2 * p) * GG + k], Wi[(2 * p + 1) * GG + k]);
    const float bhk = bh[k];
    const float bik = bi[k];

    if (k < HH) sh_h[k] = 0.0f;

    // x loader role: threads 128..147 each own one input feature slot
    const int lj = k - 128;                       // 0..19 valid
    const bool loader = (lj >= 0 && lj < DD);
    const float* src = 0;
    if (loader)
        src = (lj < NO_) ? (Yi + (size_t)n * TT * NO_ + lj)
                         : (Xh + (size_t)n * TT * NS_ + (lj - NO_));
    float xcur = 0.0f, xnext = 0.0f;
    if (loader) {
        sh_x[0][lj] = src[0];                     // x(0)
        xcur  = src[NS_];                         // x(1)   (stride 10 either way)
        xnext = src[2 * NS_];                     // x(2)
    }
    __syncthreads();

    float* hs = g_hs + (size_t)n * TT * HH;

    for (int t = 0; t < TT; t++) {
        // ---- projection phase (all 192 threads) ----
        const ulonglong2* h4 = (const ulonglong2*)sh_h;
        ull a0 = pack2(bhk, 0.0f), a1 = 0ull, a2 = 0ull, a3 = 0ull;
#pragma unroll
        for (int q = 0; q < HH / 4; q += 2) {
            const ulonglong2 hva = h4[q];
            const ulonglong2 hvb = h4[q + 1];
            a0 = fma2(hva.x, wh2[2 * q],     a0);
            a1 = fma2(hva.y, wh2[2 * q + 1], a1);
            a2 = fma2(hvb.x, wh2[2 * q + 2], a2);
            a3 = fma2(hvb.y, wh2[2 * q + 3], a3);
        }
        const float2 fh = unpack2(add2(add2(a0, a1), add2(a2, a3)));
        const float ah = fh.x + fh.y;             // h@Wh + bh

        const ull* x2 = (const ull*)sh_x[t & 1];
        ull b0 = pack2(bik, 0.0f), b1 = 0ull;
#pragma unroll
        for (int p = 0; p < DD / 2; p += 2) {
            b0 = fma2(x2[p],     wi2[p],     b0);
            b1 = fma2(x2[p + 1], wi2[p + 1], b1);
        }
        const float2 fx = unpack2(add2(b0, b1));
        const float ax = fx.x + fx.y;             // x@Wi + bi

        sh_g[k] = ax + ah;
        if (k >= 2 * HH) sh_hn[k - 2 * HH] = ah;

        // ---- gate phase: only warps 0-1 wait; others arrive and stage x ----
        if (k < HH) {
            BAR_SYNC_1();
            const float r  = sigmoid_fast(sh_g[k]);
            const float z  = sigmoid_fast(sh_g[HH + k]);
            const float hn = sh_hn[k];
            // xn + r*hn = (xn + hn) + (r-1)*hn
            const float nn = tanh_fast(fmaf(r - 1.0f, hn, sh_g[2 * HH + k]));
            const float hnew = fmaf(z, sh_h[k] - nn, nn);   // (1-z)n + z h
            sh_h[k] = hnew;
            hs[(size_t)t * HH + k] = hnew;
        } else {
            BAR_ARRIVE_1();
            if (loader) {
                if (t + 1 < TT) sh_x[(t + 1) & 1][lj] = xcur;   // x(t+1)
                xcur = xnext;
                if (t + 3 < TT) xnext = src[(size_t)(t + 3) * NS_];
            }
        }
        __syncthreads();
    }
}

// ---------------------------------------------------------------------------
// Likelihood: one thread per (n,t); FFMA2 heads, packed Cholesky in registers.
// Last block writes the final scalar (no separate finalize launch).
// ---------------------------------------------------------------------------
__global__ void __launch_bounds__(256) lik_kernel(
    const float* __restrict__ Yi, const float* __restrict__ Cw,
    const float* __restrict__ Hm, const float* __restrict__ mu_w,
    const float* __restrict__ W_mu, const float* __restrict__ b_mu,
    const float* __restrict__ W_var, const float* __restrict__ b_var,
    float* __restrict__ out)
{
    __shared__ ull sWm2[(HH / 2) * NS_];
    __shared__ ull sWv2[(HH / 2) * NS_];
    __shared__ float sH[NO_ * NS_], sbm[NS_], sbv[NS_], smw[NO_];
    __shared__ double wsum[8];

    const int tid = threadIdx.x;
    for (int i = tid; i < (HH / 2) * NS_; i += 256) {
        const int p = i / NS_, j = i - p * NS_;
        sWm2[i] = pack2(W_mu[(2 * p) * NS_ + j],  W_mu[(2 * p + 1) * NS_ + j]);
        sWv2[i] = pack2(W_var[(2 * p) * NS_ + j], W_var[(2 * p + 1) * NS_ + j]);
    }
    if (tid < NO_ * NS_) sH[tid] = Hm[tid];
    if (tid < NS_) { sbm[tid] = b_mu[tid]; sbv[tid] = b_var[tid]; }
    if (tid < NO_) smw[tid] = mu_w[tid];
    __syncthreads();

    const int idx = blockIdx.x * 256 + tid;      // grid is exact: NN*TT/256
    const int n = idx / TT;

    // heads: mu = h@W_mu + b_mu ; vr = h@W_var + b_var   (packed f32x2)
    ull mu2[NS_], vr2[NS_];
#pragma unroll
    for (int j = 0; j < NS_; j++) { mu2[j] = 0ull; vr2[j] = 0ull; }

    const ulonglong2* h4 = (const ulonglong2*)(g_hs + (size_t)idx * HH);
#pragma unroll
    for (int q = 0; q < HH / 4; q++) {
        const ulonglong2 hv = h4[q];
        const int p0 = 2 * q;
#pragma unroll
        for (int j = 0; j < NS_; j++) {
            mu2[j] = fma2(hv.x, sWm2[p0 * NS_ + j], mu2[j]);
            vr2[j] = fma2(hv.x, sWv2[p0 * NS_ + j], vr2[j]);
        }
#pragma unroll
        for (int j = 0; j < NS_; j++) {
            mu2[j] = fma2(hv.y, sWm2[(p0 + 1) * NS_ + j], mu2[j]);
            vr2[j] = fma2(hv.y, sWv2[(p0 + 1) * NS_ + j], vr2[j]);
        }
    }

    float mu[NS_], var[NS_];
#pragma unroll
    for (int j = 0; j < NS_; j++) {
        const float2 m = unpack2(mu2[j]);
        mu[j] = sbm[j] + m.x + m.y;
        const float2 v = unpack2(vr2[j]);
        const float x = sbv[j] + v.x + v.y;
        var[j] = (x > 15.0f) ? x : __logf(1.0f + __expf(x));   // softplus
    }

    // residual e = y - (H mu + mu_w)
    float e[NO_];
#pragma unroll
    for (int i = 0; i < NO_; i++) {
        float m = smw[i];
#pragma unroll
        for (int j = 0; j < NS_; j++) m = fmaf(sH[i * NS_ + j], mu[j], m);
        e[i] = Yi[(size_t)idx * NO_ + i] - m;
    }

    // A = H diag(var) H^T + Cw, packed lower triangle
    float A[NO_ * (NO_ + 1) / 2];
    const float* cw = Cw + (size_t)n * NO_ * NO_;
#pragma unroll
    for (int i = 0; i < NO_; i++)
#pragma unroll
        for (int kk = 0; kk <= i; kk++)
            A[i * (i + 1) / 2 + kk] = cw[i * NO_ + kk];
#pragma unroll
    for (int j = 0; j < NS_; j++) {
        const float vj = var[j];
        float hj[NO_];
#pragma unroll
        for (int i = 0; i < NO_; i++) hj[i] = sH[i * NS_ + j];
#pragma unroll
        for (int i = 0; i < NO_; i++) {
            const float hv = hj[i] * vj;
#pragma unroll
            for (int kk = 0; kk <= i; kk++)
                A[i * (i + 1) / 2 + kk] = fmaf(hv, hj[kk], A[i * (i + 1) / 2 + kk]);
        }
    }

    // in-place packed Cholesky; logdet = sum log(s_i) since Lii^2 = s_i
    float rdi[NO_];
    float logdet = 0.0f;
#pragma unroll
    for (int i = 0; i < NO_; i++) {
#pragma unroll
        for (int kk = 0; kk < i; kk++) {
            float s = A[i * (i + 1) / 2 + kk];
#pragma unroll
            for (int j2 = 0; j2 < NO_; j2++)
                if (j2 < kk)
                    s -= A[i * (i + 1) / 2 + j2] * A[kk * (kk + 1) / 2 + j2];
            A[i * (i + 1) / 2 + kk] = s * rdi[kk];
        }
        float s = A[i * (i + 1) / 2 + i];
#pragma unroll
        for (int j2 = 0; j2 < NO_; j2++)
            if (j2 < i) {
                const float l = A[i * (i + 1) / 2 + j2];
                s -= l * l;
            }
        rdi[i] = rsqrtf(s);
        logdet += __logf(s);
    }

    // forward solve z = L^{-1} e ; quad = |z|^2
    float quad = 0.0f;
    float zv[NO_];
#pragma unroll
    for (int i = 0; i < NO_; i++) {
        float s = e[i];
#pragma unroll
        for (int j2 = 0; j2 < NO_; j2++)
            if (j2 < i) s -= A[i * (i + 1) / 2 + j2] * zv[j2];
        zv[i] = s * rdi[i];
        quad = fmaf(zv[i], zv[i], quad);
    }

    double local = (double)(logdet + quad);

    // block reduction -> one atomicAdd; last block finalizes
    for (int off = 16; off > 0; off >>= 1)
        local += __shfl_down_sync(0xffffffffu, local, off);
    if ((tid & 31) == 0) wsum[tid >> 5] = local;
    __syncthreads();
    if (tid == 0) {
        double s = 0.0;
#pragma unroll
        for (int w = 0; w < 8; w++) s += wsum[w];
        atomicAdd(&g_acc, s);
        __threadfence();
        const unsigned int d = atomicAdd(&g_done, 1u);
        if (d == gridDim.x - 1) {
            __threadfence();
            const double LOG2PI = 1.8378770664093453;
            const double acc = *((volatile double*)&g_acc);
            out[0] = (float)(-0.5 * LOG2PI - 0.5 * acc / ((double)NN * TT * NO_));
        }
    }
}

extern "C" void kernel_launch(void* const* d_in, const int* in_sizes, int n_in,
                              void* d_out, int out_size)
{
    const float* Yi    = (const float*)d_in[0];
    const float* Xh    = (const float*)d_in[1];
    const float* Cw    = (const float*)d_in[2];
    const float* Hm    = (const float*)d_in[3];
    const float* mu_w  = (const float*)d_in[4];
    const float* Wi    = (const float*)d_in[5];
    const float* Wh    = (const float*)d_in[6];
    const float* bi    = (const float*)d_in[7];
    const float* bh    = (const float*)d_in[8];
    const float* W_mu  = (const float*)d_in[9];
    const float* b_mu  = (const float*)d_in[10];
    const float* W_var = (const float*)d_in[11];
    const float* b_var = (const float*)d_in[12];
    float* out = (float*)d_out;

    gru_scan_kernel<<<NN, GG>>>(Yi, Xh, Wi, Wh, bi, bh);
    lik_kernel<<<NN * TT / 256, 256>>>(Yi, Cw, Hm, mu_w, W_mu, b_mu, W_var, b_var, out);
}